// round 5
// baseline (speedup 1.0000x reference)
#include <cuda_runtime.h>

// ---------------- problem constants ----------------
#define LYR   8
#define BB    8
#define CCH   64
#define HH    96
#define WW    96
#define HWN   (HH*WW)        // 9216
#define CHW   (CCH*HWN)      // 589824
#define BCHW_N (BB*CHW)      // 4718592
#define NTILE 36             // (96/16)^2 spatial tiles
#define EPSV  1e-5f

// ---------------- scratch (device globals; no runtime allocs) ----------------
__device__ float g_Z [LYR*BCHW_N];   // 151 MB
__device__ float g_dZ[LYR*BCHW_N];   // 151 MB
__device__ float g_Y [LYR*BCHW_N];   // 151 MB
__device__ float g_psum  [LYR*BB*CCH*NTILE];
__device__ float g_psumsq[LYR*BB*CCH*NTILE];
__device__ float g_stats [LYR*BB*CCH*2];   // (mean, rsqrt(var+eps))

// ============================================================================
// Conv kernel.
// MODE 0: dZ = conv2d(Z, K, pad=1); also write per-(l,b,co,tile) partial sums
// MODE 1: Y = -conv2d(lrelu(inorm(dZ)), Kt, pad=1), Kt[o,i,kh,kw]=K[i,o,2-kh,2-kw]
//         NOTE: zero padding is applied AFTER inorm+lrelu — out-of-image halo
//         values must remain exactly 0 (bug fixed this round).
// Block: one 16x16 spatial tile of one (l,b); 256 threads; all 64 out-channels.
// Thread: 8 co x 8 contiguous-W pixels in registers.
// ============================================================================
template<int MODE>
__global__ void __launch_bounds__(256, 2) conv_kernel(const float* __restrict__ Kw)
{
    const int tileIdx = blockIdx.x;          // 0..35
    const int b       = blockIdx.y;
    const int l       = blockIdx.z;
    const int tY = tileIdx / 6, tX = tileIdx - tY*6;
    const int gh0 = tY*16, gw0 = tX*16;

    const int tid = threadIdx.x;
    const int cog = tid >> 5;                // 0..7 : output-channel group (== warp id)
    const int pp  = tid & 31;                // pixel position within tile
    const int row = pp >> 1;                 // 0..15
    const int col = (pp & 1) << 3;           // 0 or 8

    __shared__ float sIn[18*19];             // 18x18 halo tile, padded stride 19
    __shared__ float sK [CCH*9];             // kernel slice for current ci

    const int lb = l*BB + b;
    const float* __restrict__ gin  = (MODE==0 ? g_Z  : g_dZ) + (size_t)lb*CHW;
    float*       __restrict__ gout = (MODE==0 ? g_dZ : g_Y ) + (size_t)lb*CHW;
    const float* __restrict__ Kl   = Kw + (size_t)l*CCH*CCH*9;

    // ---- input tile load geometry (each thread loads <=2 halo elements) ----
    const int r0 = tid / 18, c0 = tid - r0*18;
    const int idx1 = tid + 256;
    const int r1 = idx1 / 18, c1 = idx1 - r1*18;
    const bool has1 = (idx1 < 324);
    const int gh_0 = gh0 - 1 + r0, gw_0 = gw0 - 1 + c0;
    const int gh_1 = gh0 - 1 + r1, gw_1 = gw0 - 1 + c1;
    const bool ok0 = (gh_0>=0)&&(gh_0<HH)&&(gw_0>=0)&&(gw_0<WW);
    const bool ok1 = has1 && (gh_1>=0)&&(gh_1<HH)&&(gw_1>=0)&&(gw_1<WW);
    const int goff0 = gh_0*WW + gw_0;
    const int goff1 = gh_1*WW + gw_1;
    const int spos0 = r0*19 + c0;
    const int spos1 = r1*19 + c1;

    // ---- kernel slice load geometry (576 values, 3 per thread) ----
    int kpos0, kpos1, kpos2;   // smem store positions
    int kg0, kg1, kg2;         // per-ci gmem offsets
    const bool hask2 = (tid + 512) < 576;
    {
        int i0 = tid, i1 = tid+256, i2 = tid+512;
        int co, k;
        if (MODE == 0) {
            // sK[co*9+k] = Kl[(co*64+ci)*9 + k]   (addr = Kl + ci*9 + kg)
            co = i0/9; k = i0-co*9; kpos0 = i0; kg0 = co*(CCH*9) + k;
            co = i1/9; k = i1-co*9; kpos1 = i1; kg1 = co*(CCH*9) + k;
            co = i2/9; k = i2-co*9; kpos2 = i2; kg2 = co*(CCH*9) + k;
        } else {
            // sK[co*9+(8-k)] = Kl[(ci*64)*9 + co*9 + k]  (addr = Kl + ci*576 + kg)
            co = i0/9; k = i0-co*9; kpos0 = co*9 + (8-k); kg0 = i0;
            co = i1/9; k = i1-co*9; kpos1 = co*9 + (8-k); kg1 = i1;
            co = i2/9; k = i2-co*9; kpos2 = co*9 + (8-k); kg2 = i2;
        }
    }

    float acc[8][8];
    #pragma unroll
    for (int j=0;j<8;j++)
        #pragma unroll
        for (int p=0;p<8;p++) acc[j][p] = 0.f;

    float pin0, pin1, pk0, pk1, pk2;
    auto prefetch = [&](int ci) {
        const float* src = gin + (size_t)ci*HWN;
        float v0 = ok0 ? __ldg(src + goff0) : 0.f;
        float v1 = ok1 ? __ldg(src + goff1) : 0.f;
        if (MODE == 1) {
            // normalize + lrelu ONLY in-image values; zero padding stays zero
            float mean = g_stats[(lb*CCH + ci)*2 + 0];
            float rs   = g_stats[(lb*CCH + ci)*2 + 1];
            if (ok0) { v0 = (v0 - mean) * rs;  v0 = (v0 >= 0.f) ? v0 : 0.2f*v0; }
            if (ok1) { v1 = (v1 - mean) * rs;  v1 = (v1 >= 0.f) ? v1 : 0.2f*v1; }
        }
        pin0 = v0; pin1 = v1;
        const float* kp = (MODE==0) ? (Kl + ci*9) : (Kl + ci*(CCH*9));
        pk0 = __ldg(kp + kg0);
        pk1 = __ldg(kp + kg1);
        pk2 = hask2 ? __ldg(kp + kg2) : 0.f;
    };

    prefetch(0);
    for (int ci = 0; ci < CCH; ci++) {
        __syncthreads();                 // previous compute done -> smem reusable
        sIn[spos0] = pin0;
        if (has1) sIn[spos1] = pin1;
        sK[kpos0] = pk0;
        sK[kpos1] = pk1;
        if (hask2) sK[kpos2] = pk2;
        __syncthreads();
        if (ci + 1 < CCH) prefetch(ci + 1);

        #pragma unroll
        for (int dr = 0; dr < 3; dr++) {
            float v[10];
            #pragma unroll
            for (int x = 0; x < 10; x++) v[x] = sIn[(row+dr)*19 + col + x];
            #pragma unroll
            for (int dc = 0; dc < 3; dc++) {
                #pragma unroll
                for (int j = 0; j < 8; j++) {
                    float kv = sK[(cog*8 + j)*9 + dr*3 + dc];   // warp-broadcast
                    #pragma unroll
                    for (int p = 0; p < 8; p++)
                        acc[j][p] = fmaf(kv, v[p+dc], acc[j][p]);
                }
            }
        }
    }

    // ---- epilogue: store (+ partial stats for MODE 0) ----
    const int ghr = gh0 + row;
    const int gwc = gw0 + col;
    #pragma unroll
    for (int j = 0; j < 8; j++) {
        const int co = cog*8 + j;
        float o[8];
        #pragma unroll
        for (int p = 0; p < 8; p++) o[p] = (MODE==1) ? -acc[j][p] : acc[j][p];
        float* dst = gout + (size_t)co*HWN + ghr*WW + gwc;
        reinterpret_cast<float4*>(dst)[0] = make_float4(o[0],o[1],o[2],o[3]);
        reinterpret_cast<float4*>(dst)[1] = make_float4(o[4],o[5],o[6],o[7]);

        if (MODE == 0) {
            float s = 0.f, q = 0.f;
            #pragma unroll
            for (int p = 0; p < 8; p++) { s += acc[j][p]; q += acc[j][p]*acc[j][p]; }
            #pragma unroll
            for (int off = 16; off > 0; off >>= 1) {
                s += __shfl_xor_sync(0xffffffffu, s, off);
                q += __shfl_xor_sync(0xffffffffu, q, off);
            }
            if (pp == 0) {   // deterministic per-(l,b,co,tile) partials, no atomics
                g_psum  [(lb*CCH + co)*NTILE + tileIdx] = s;
                g_psumsq[(lb*CCH + co)*NTILE + tileIdx] = q;
            }
        }
    }
}

// ---------------- finalize instance-norm stats ----------------
__global__ void stats_kernel()
{
    int i = blockIdx.x*blockDim.x + threadIdx.x;
    if (i >= LYR*BB*CCH) return;
    float s = 0.f, q = 0.f;
    #pragma unroll
    for (int t = 0; t < NTILE; t++) { s += g_psum[i*NTILE+t]; q += g_psumsq[i*NTILE+t]; }
    float mean = s * (1.f/HWN);
    float var  = q * (1.f/HWN) - mean*mean;
    g_stats[i*2 + 0] = mean;
    g_stats[i*2 + 1] = rsqrtf(var + EPSV);
}

// ---------------- tri-diagonal scans (elementwise over layers) ----------------
// mode 0: Z -> g_Z ; mode 1: head=out[0:BCHW], Z=out[BCHW:9*BCHW]
// mode 2: Z -> out ; mode 3: head -> out, Z -> g_Z
__global__ void scan_kernel(const float* __restrict__ X, const float* __restrict__ X0,
                            int useY, int mode, float* __restrict__ out)
{
    const int N4 = BCHW_N/4;
    int e = blockIdx.x*blockDim.x + threadIdx.x;
    if (e >= N4) return;

    float4* Zb;
    float4* head = nullptr;
    if      (mode == 0) { Zb = (float4*)g_Z; }
    else if (mode == 1) { Zb = (float4*)(out + BCHW_N); head = (float4*)out; }
    else if (mode == 2) { Zb = (float4*)out; }
    else                { Zb = (float4*)g_Z; head = (float4*)out; }

    const float4* Y4 = (const float4*)g_Y;
    float4 x0 = reinterpret_cast<const float4*>(X0)[e % (CHW/4)];
    float4 xx = reinterpret_cast<const float4*>(X )[e];

    float fx[8], fy[8], fz[8], fw[8];
    float cx=0.f, cy=0.f, cz=0.f, cw=0.f;
    #pragma unroll
    for (int i = 0; i < 8; i++) {
        float ai = sqrtf((float)(i+1) / (float)(i+2));
        float bi = sqrtf((float)i / (float)(i+1));
        float4 y = make_float4(0.f,0.f,0.f,0.f);
        if (useY) y = Y4[(size_t)i*N4 + e];
        if (i == 0) { y.x+=x0.x; y.y+=x0.y; y.z+=x0.z; y.w+=x0.w; }
        if (i == 7) { y.x+=xx.x; y.y+=xx.y; y.z+=xx.z; y.w+=xx.w; }
        cx = ai*(bi*cx + y.x);
        cy = ai*(bi*cy + y.y);
        cz = ai*(bi*cz + y.z);
        cw = ai*(bi*cw + y.w);
        fx[i]=cx; fy[i]=cy; fz[i]=cz; fw[i]=cw;
    }
    cx=cy=cz=cw=0.f;
    #pragma unroll
    for (int i = 7; i >= 0; i--) {
        float ai = sqrtf((float)(i+1) / (float)(i+2));
        cx = ai*(ai*cx + fx[i]);
        cy = ai*(ai*cy + fy[i]);
        cz = ai*(ai*cz + fz[i]);
        cw = ai*(ai*cw + fw[i]);
        float4 z = make_float4(cx,cy,cz,cw);
        Zb[(size_t)i*N4 + e] = z;
        if (i == 7 && head) head[e] = z;
    }
}

// ---------------- launcher ----------------
extern "C" void kernel_launch(void* const* d_in, const int* in_sizes, int n_in,
                              void* d_out, int out_size)
{
    const float *X = nullptr, *Kw = nullptr, *X0 = nullptr;
    for (int i = 0; i < n_in; i++) {
        if      (in_sizes[i] == BCHW_N)        X  = (const float*)d_in[i];
        else if (in_sizes[i] == LYR*CCH*CCH*9) Kw = (const float*)d_in[i];
        else if (in_sizes[i] == CHW)           X0 = (const float*)d_in[i];
    }
    float* out = (float*)d_out;

    dim3 cgrid(NTILE, BB, LYR);
    const int sgrid    = (BCHW_N/4 + 255) / 256;
    const int statGrid = (LYR*BB*CCH + 255) / 256;

    int finalMode;
    if      (out_size >= 9*BCHW_N) finalMode = 1;   // (Z[-1], Z) concatenated
    else if (out_size >= 8*BCHW_N) finalMode = 2;   // Z only
    else                           finalMode = 3;   // Z[-1] only

    // iteration 0: Z is all-zero -> layer output is exactly zero -> scan with Y=0
    scan_kernel<<<sgrid, 256>>>(X, X0, /*useY=*/0, /*mode=*/0, out);

    for (int it = 1; it < 4; it++) {
        conv_kernel<0><<<cgrid, 256>>>(Kw);
        stats_kernel<<<statGrid, 256>>>();
        conv_kernel<1><<<cgrid, 256>>>(Kw);
        int mode = (it == 3) ? finalMode : 0;
        scan_kernel<<<sgrid, 256>>>(X, X0, /*useY=*/1, mode, out);
    }
}